// round 1
// baseline (speedup 1.0000x reference)
#include <cuda_runtime.h>

#define NN 100000
#define EE 3200000
#define RR 8

// ---- scratch (device globals; no allocation allowed) ----
__device__ __align__(16) int   g_cnt[NN * RR];          // per-(dst, rel) edge counts
__device__ __align__(16) float g_T[NN * RR * 16];       // per-node per-relation transformed features
__device__ __align__(16) float g_agg1[NN * 16];         // layer-1 accumulator

// ---- weights in constant memory (uniform access -> LDCU + UR-operand FFMA) ----
__constant__ float cW1[RR * 16 * 16];
__constant__ float cR1[16 * 16];
__constant__ float cB1[16];
__constant__ float cW2[RR * 16 * 16];
__constant__ float cR2[16 * 16];
__constant__ float cB2[16];

__global__ void k_zero_cnt() {
    int i = blockIdx.x * blockDim.x + threadIdx.x;
    if (i < NN * RR) g_cnt[i] = 0;
}

__global__ void k_count(const int* __restrict__ dst, const int* __restrict__ et) {
    int e = blockIdx.x * blockDim.x + threadIdx.x;
    if (e < EE) atomicAdd(&g_cnt[dst[e] * RR + et[e]], 1);
}

// Per node: T[i][r][:] = x_i @ W_r for all r, agg[i][:] = x_i @ root + b.
// L==2 applies relu to the input row first.
template <int L>
__global__ void __launch_bounds__(256) k_transform(const float* __restrict__ xin,
                                                   float* __restrict__ T,
                                                   float* __restrict__ agg) {
    int i = blockIdx.x * blockDim.x + threadIdx.x;
    if (i >= NN) return;

    float x[16];
    const float4* xr = (const float4*)(xin + i * 16);
#pragma unroll
    for (int j = 0; j < 4; j++) {
        float4 v = __ldg(xr + j);
        x[4 * j + 0] = v.x; x[4 * j + 1] = v.y; x[4 * j + 2] = v.z; x[4 * j + 3] = v.w;
    }
    if (L == 2) {
#pragma unroll
        for (int k = 0; k < 16; k++) x[k] = fmaxf(x[k], 0.0f);
    }

    float4* Trow = (float4*)(T + i * (RR * 16));
#pragma unroll
    for (int r = 0; r < RR; r++) {
        float acc[16];
#pragma unroll
        for (int c = 0; c < 16; c++) acc[c] = 0.0f;
#pragma unroll
        for (int k = 0; k < 16; k++) {
            float xv = x[k];
#pragma unroll
            for (int c = 0; c < 16; c++) {
                float w = (L == 1) ? cW1[(r * 16 + k) * 16 + c] : cW2[(r * 16 + k) * 16 + c];
                acc[c] = fmaf(xv, w, acc[c]);
            }
        }
#pragma unroll
        for (int j = 0; j < 4; j++)
            Trow[r * 4 + j] = make_float4(acc[4 * j], acc[4 * j + 1], acc[4 * j + 2], acc[4 * j + 3]);
    }

    // self-loop: x @ root + bias
    {
        float acc[16];
#pragma unroll
        for (int c = 0; c < 16; c++) acc[c] = (L == 1) ? cB1[c] : cB2[c];
#pragma unroll
        for (int k = 0; k < 16; k++) {
            float xv = x[k];
#pragma unroll
            for (int c = 0; c < 16; c++) {
                float w = (L == 1) ? cR1[k * 16 + c] : cR2[k * 16 + c];
                acc[c] = fmaf(xv, w, acc[c]);
            }
        }
        float4* arow = (float4*)(agg + i * 16);
#pragma unroll
        for (int j = 0; j < 4; j++)
            arow[j] = make_float4(acc[4 * j], acc[4 * j + 1], acc[4 * j + 2], acc[4 * j + 3]);
    }
}

// Per edge: agg[dst] += T[src][etype] * (1/cnt[dst,etype]) via vectorized red.
__global__ void __launch_bounds__(256) k_edge(const int* __restrict__ src,
                                              const int* __restrict__ dst,
                                              const int* __restrict__ et,
                                              const float* __restrict__ T,
                                              float* __restrict__ agg) {
    int e = blockIdx.x * blockDim.x + threadIdx.x;
    if (e >= EE) return;
    int s = __ldg(src + e);
    int d = __ldg(dst + e);
    int r = __ldg(et + e);
    int cn = g_cnt[d * RR + r];
    float norm = 1.0f / (float)cn;  // cn >= 1: this edge itself was counted
    const float4* t = (const float4*)(T + s * (RR * 16) + r * 16);
    float* a = agg + d * 16;
#pragma unroll
    for (int j = 0; j < 4; j++) {
        float4 v = __ldg(t + j);
        asm volatile("red.global.add.v4.f32 [%0], {%1, %2, %3, %4};"
                     :: "l"(a + 4 * j),
                        "f"(v.x * norm), "f"(v.y * norm), "f"(v.z * norm), "f"(v.w * norm)
                     : "memory");
    }
}

__global__ void k_logsoftmax(float* __restrict__ out) {
    int i = blockIdx.x * blockDim.x + threadIdx.x;
    if (i >= NN) return;
    float4* row = (float4*)(out + i * 16);
    float v[16];
#pragma unroll
    for (int j = 0; j < 4; j++) {
        float4 t = row[j];
        v[4 * j + 0] = t.x; v[4 * j + 1] = t.y; v[4 * j + 2] = t.z; v[4 * j + 3] = t.w;
    }
    float m = v[0];
#pragma unroll
    for (int k = 1; k < 16; k++) m = fmaxf(m, v[k]);
    float s = 0.0f;
#pragma unroll
    for (int k = 0; k < 16; k++) s += expf(v[k] - m);
    float l = m + logf(s);
#pragma unroll
    for (int j = 0; j < 4; j++)
        row[j] = make_float4(v[4 * j] - l, v[4 * j + 1] - l, v[4 * j + 2] - l, v[4 * j + 3] - l);
}

extern "C" void kernel_launch(void* const* d_in, const int* in_sizes, int n_in,
                              void* d_out, int out_size) {
    const float* embed = (const float*)d_in[0];
    const float* W1    = (const float*)d_in[1];
    const float* root1 = (const float*)d_in[2];
    const float* b1    = (const float*)d_in[3];
    const float* W2    = (const float*)d_in[4];
    const float* root2 = (const float*)d_in[5];
    const float* b2    = (const float*)d_in[6];
    const int*   ei    = (const int*)d_in[7];   // [2, E]
    const int*   et    = (const int*)d_in[8];   // [E]
    const int* src = ei;
    const int* dst = ei + EE;
    float* out = (float*)d_out;

    (void)in_sizes; (void)n_in; (void)out_size;

    // weights -> constant memory (DtoD async copies; graph-capturable)
    cudaMemcpyToSymbolAsync(cW1, W1,    RR * 256 * sizeof(float), 0, cudaMemcpyDeviceToDevice, 0);
    cudaMemcpyToSymbolAsync(cR1, root1, 256 * sizeof(float),      0, cudaMemcpyDeviceToDevice, 0);
    cudaMemcpyToSymbolAsync(cB1, b1,    16 * sizeof(float),       0, cudaMemcpyDeviceToDevice, 0);
    cudaMemcpyToSymbolAsync(cW2, W2,    RR * 256 * sizeof(float), 0, cudaMemcpyDeviceToDevice, 0);
    cudaMemcpyToSymbolAsync(cR2, root2, 256 * sizeof(float),      0, cudaMemcpyDeviceToDevice, 0);
    cudaMemcpyToSymbolAsync(cB2, b2,    16 * sizeof(float),       0, cudaMemcpyDeviceToDevice, 0);

    const int TB = 256;
    k_zero_cnt<<<(NN * RR + TB - 1) / TB, TB>>>();
    k_count<<<(EE + TB - 1) / TB, TB>>>(dst, et);

    // layer 1
    k_transform<1><<<(NN + TB - 1) / TB, TB>>>(embed, g_T, g_agg1);
    k_edge<<<(EE + TB - 1) / TB, TB>>>(src, dst, et, g_T, g_agg1);

    // layer 2 (relu fused into transform input; writes self-term straight to d_out)
    k_transform<2><<<(NN + TB - 1) / TB, TB>>>(g_agg1, g_T, out);
    k_edge<<<(EE + TB - 1) / TB, TB>>>(src, dst, et, g_T, out);

    // in-place log-softmax on d_out
    k_logsoftmax<<<(NN + TB - 1) / TB, TB>>>(out);
}

// round 2
// speedup vs baseline: 9.0365x; 9.0365x over previous
#include <cuda_runtime.h>

#define NN 100000
#define EE 3200000
#define RR 8
#define NB (NN * RR)                 // 800000 sort keys (dst*8+rel)
#define SCAN_BLK 1024
#define SCAN_ITEMS 4
#define SCAN_CHUNK (SCAN_BLK * SCAN_ITEMS)              // 4096
#define SCAN_NBLK ((NB + SCAN_CHUNK - 1) / SCAN_CHUNK)  // 196

// ---- device scratch (no allocation allowed) ----
__device__ __align__(16) int   g_cnt[NB];
__device__ __align__(16) int   g_off[NB + 1];
__device__ __align__(16) int   g_bsum[SCAN_NBLK];
__device__ __align__(16) int   g_boff[SCAN_NBLK];
__device__ __align__(16) int   g_pos[EE];
__device__ __align__(16) int   g_srt[EE];
__device__ __align__(16) float g_h[NN * 16];

__global__ void k_zero_cnt() {
    int i = blockIdx.x * blockDim.x + threadIdx.x;
    if (i < NB) g_cnt[i] = 0;
}

// One int atomic per edge: count + within-bucket position.
__global__ void k_hist(const int* __restrict__ dst, const int* __restrict__ et) {
    int e = blockIdx.x * blockDim.x + threadIdx.x;
    if (e >= EE) return;
    int key = dst[e] * RR + et[e];
    g_pos[e] = atomicAdd(&g_cnt[key], 1);
}

// ---- exclusive scan of g_cnt -> g_off (3 kernels, no atomics) ----
__global__ void k_scan_reduce() {
    __shared__ int sh[SCAN_BLK];
    int t = threadIdx.x, b = blockIdx.x;
    int i0 = b * SCAN_CHUNK + t * SCAN_ITEMS;
    int s = 0;
#pragma unroll
    for (int j = 0; j < SCAN_ITEMS; j++) {
        int i = i0 + j;
        s += (i < NB) ? g_cnt[i] : 0;
    }
    sh[t] = s;
    __syncthreads();
    for (int ofs = SCAN_BLK / 2; ofs > 0; ofs >>= 1) {
        if (t < ofs) sh[t] += sh[t + ofs];
        __syncthreads();
    }
    if (t == 0) g_bsum[b] = sh[0];
}

__global__ void k_scan_mid() {
    int run = 0;
    for (int i = 0; i < SCAN_NBLK; i++) {
        g_boff[i] = run;
        run += g_bsum[i];
    }
    g_off[NB] = run;  // == EE
}

__global__ void k_scan_write() {
    __shared__ int sh[SCAN_BLK];
    int t = threadIdx.x, b = blockIdx.x;
    int i0 = b * SCAN_CHUNK + t * SCAN_ITEMS;
    int v[SCAN_ITEMS];
    int tot = 0;
#pragma unroll
    for (int j = 0; j < SCAN_ITEMS; j++) {
        int i = i0 + j;
        v[j] = (i < NB) ? g_cnt[i] : 0;
        tot += v[j];
    }
    sh[t] = tot;
    __syncthreads();
    // Hillis-Steele inclusive scan over thread totals
    for (int ofs = 1; ofs < SCAN_BLK; ofs <<= 1) {
        int add = (t >= ofs) ? sh[t - ofs] : 0;
        __syncthreads();
        sh[t] += add;
        __syncthreads();
    }
    int base = g_boff[b] + sh[t] - tot;  // exclusive
#pragma unroll
    for (int j = 0; j < SCAN_ITEMS; j++) {
        int i = i0 + j;
        if (i < NB) g_off[i] = base;
        base += v[j];
    }
}

// Atomic-free scatter: place src of edge e into its bucket slot.
__global__ void k_scatter(const int* __restrict__ src, const int* __restrict__ dst,
                          const int* __restrict__ et) {
    int e = blockIdx.x * blockDim.x + threadIdx.x;
    if (e >= EE) return;
    int key = dst[e] * RR + et[e];
    g_srt[g_off[key] + g_pos[e]] = src[e];
}

// Gather-based RGCN layer: thread per dst node, zero atomics.
// out_i = sum_r (1/n_r) * (sum_{j in N_r(i)} x_j) @ W_r  +  x_i @ root + b
// L==1: relu epilogue; L==2: log-softmax epilogue.
template <int L>
__global__ void __launch_bounds__(128) k_agg(const float* __restrict__ xin,
                                             const float* __restrict__ W,
                                             const float* __restrict__ root,
                                             const float* __restrict__ bias,
                                             float* __restrict__ out) {
    __shared__ float sW[RR * 256];
    __shared__ float sR[256];
    __shared__ float sB[16];
    int t = threadIdx.x;
    for (int i = t; i < RR * 256; i += blockDim.x) sW[i] = __ldg(W + i);
    for (int i = t; i < 256; i += blockDim.x) sR[i] = __ldg(root + i);
    if (t < 16) sB[t] = __ldg(bias + t);
    __syncthreads();

    int d = blockIdx.x * blockDim.x + t;
    if (d >= NN) return;

    float acc[16];
#pragma unroll
    for (int c = 0; c < 16; c++) acc[c] = sB[c];

    // self term: x_d @ root
    {
        const float4* xr = (const float4*)(xin + (size_t)d * 16);
        float xs[16];
#pragma unroll
        for (int j = 0; j < 4; j++) {
            float4 w = __ldg(xr + j);
            xs[4 * j] = w.x; xs[4 * j + 1] = w.y; xs[4 * j + 2] = w.z; xs[4 * j + 3] = w.w;
        }
#pragma unroll
        for (int k = 0; k < 16; k++) {
            float xv = xs[k];
#pragma unroll
            for (int c = 0; c < 16; c++) acc[c] = fmaf(xv, sR[k * 16 + c], acc[c]);
        }
    }

    // relation groups (edges pre-sorted by key = d*8+r)
    int base = d * RR;
    int o0 = g_off[base];
#pragma unroll 1
    for (int r = 0; r < RR; r++) {
        int o1 = g_off[base + r + 1];
        int n = o1 - o0;
        if (n > 0) {
            float sum[16];
#pragma unroll
            for (int c = 0; c < 16; c++) sum[c] = 0.0f;
            for (int i = o0; i < o1; i++) {
                int s = __ldg(g_srt + i);
                const float4* p = (const float4*)(xin + (size_t)s * 16);
#pragma unroll
                for (int j = 0; j < 4; j++) {
                    float4 w = __ldg(p + j);
                    sum[4 * j] += w.x; sum[4 * j + 1] += w.y;
                    sum[4 * j + 2] += w.z; sum[4 * j + 3] += w.w;
                }
            }
            float inv = 1.0f / (float)n;
            const float* Wr = sW + r * 256;
#pragma unroll
            for (int k = 0; k < 16; k++) {
                float v = sum[k] * inv;
#pragma unroll
                for (int c = 0; c < 16; c++) acc[c] = fmaf(v, Wr[k * 16 + c], acc[c]);
            }
        }
        o0 = o1;
    }

    float4* orow = (float4*)(out + (size_t)d * 16);
    if (L == 1) {
#pragma unroll
        for (int c = 0; c < 16; c++) acc[c] = fmaxf(acc[c], 0.0f);
    } else {
        float m = acc[0];
#pragma unroll
        for (int c = 1; c < 16; c++) m = fmaxf(m, acc[c]);
        float s = 0.0f;
#pragma unroll
        for (int c = 0; c < 16; c++) s += expf(acc[c] - m);
        float l = m + logf(s);
#pragma unroll
        for (int c = 0; c < 16; c++) acc[c] -= l;
    }
#pragma unroll
    for (int j = 0; j < 4; j++)
        orow[j] = make_float4(acc[4 * j], acc[4 * j + 1], acc[4 * j + 2], acc[4 * j + 3]);
}

extern "C" void kernel_launch(void* const* d_in, const int* in_sizes, int n_in,
                              void* d_out, int out_size) {
    const float* embed = (const float*)d_in[0];
    const float* W1    = (const float*)d_in[1];
    const float* root1 = (const float*)d_in[2];
    const float* b1    = (const float*)d_in[3];
    const float* W2    = (const float*)d_in[4];
    const float* root2 = (const float*)d_in[5];
    const float* b2    = (const float*)d_in[6];
    const int*   ei    = (const int*)d_in[7];   // [2, E]
    const int*   et    = (const int*)d_in[8];   // [E]
    const int* src = ei;
    const int* dst = ei + EE;
    float* out = (float*)d_out;
    (void)in_sizes; (void)n_in; (void)out_size;

    const int TB = 256;

    // build CSR by (dst, rel) — shared by both layers
    k_zero_cnt<<<(NB + TB - 1) / TB, TB>>>();
    k_hist<<<(EE + TB - 1) / TB, TB>>>(dst, et);
    k_scan_reduce<<<SCAN_NBLK, SCAN_BLK>>>();
    k_scan_mid<<<1, 1>>>();
    k_scan_write<<<SCAN_NBLK, SCAN_BLK>>>();
    k_scatter<<<(EE + TB - 1) / TB, TB>>>(src, dst, et);

    // layer 1 (relu fused), layer 2 (log-softmax fused)
    k_agg<1><<<(NN + 127) / 128, 128>>>(embed, W1, root1, b1, g_h);
    k_agg<2><<<(NN + 127) / 128, 128>>>(g_h, W2, root2, b2, out);
}